// round 1
// baseline (speedup 1.0000x reference)
#include <cuda_runtime.h>

#define NFFT   512
#define NOUT   257
#define NBATCH 32768

// One block = one row. 256 threads, radix-2 DIT FFT of 512 real samples
// in shared memory, then write bins 0..256 (re, im).
__global__ __launch_bounds__(256)
void rfft512_kernel(const float* __restrict__ x,
                    float* __restrict__ yre,
                    float* __restrict__ yim)
{
    __shared__ float sr[NFFT];
    __shared__ float si[NFFT];
    __shared__ float twc[NFFT / 2];
    __shared__ float tws[NFFT / 2];

    const int t = threadIdx.x;                    // 0..255
    const long long row = blockIdx.x;

    // Twiddle table: W_512^t = exp(-2*pi*i * t / 512), t = 0..255
    {
        float ang = -6.2831853071795864769f * (float)t / (float)NFFT;
        float s, c;
        sincosf(ang, &s, &c);
        twc[t] = c;
        tws[t] = s;
    }

    // Coalesced load of two samples per thread; scatter to bit-reversed slots.
    const float2 v = *reinterpret_cast<const float2*>(x + row * NFFT + 2 * t);
    const int n0 = 2 * t;
    const int n1 = 2 * t + 1;
    const int r0 = __brev((unsigned)n0) >> 23;    // 9-bit reversal
    const int r1 = __brev((unsigned)n1) >> 23;
    sr[r0] = v.x; si[r0] = 0.0f;
    sr[r1] = v.y; si[r1] = 0.0f;
    __syncthreads();

    // 9 DIT stages. Each thread owns exactly one disjoint butterfly pair per
    // stage, so a single barrier per stage suffices.
    #pragma unroll
    for (int s = 0; s < 9; ++s) {
        const int half = 1 << s;
        const int j    = t & (half - 1);
        const int i0   = ((t >> s) << (s + 1)) + j;
        const int i1   = i0 + half;
        const int twi  = j << (8 - s);            // j * (512 / (2*half))

        const float c  = twc[twi];
        const float sn = tws[twi];

        const float vr = sr[i1];
        const float vi = si[i1];
        const float tr = vr * c - vi * sn;
        const float ti = vr * sn + vi * c;
        const float ur = sr[i0];
        const float ui = si[i0];

        sr[i0] = ur + tr;  si[i0] = ui + ti;
        sr[i1] = ur - tr;  si[i1] = ui - ti;
        __syncthreads();
    }

    // Write bins 0..255 (one per thread), thread 0 also writes Nyquist bin 256.
    const long long ob = row * NOUT;
    yre[ob + t] = sr[t];
    yim[ob + t] = si[t];
    if (t == 0) {
        yre[ob + 256] = sr[256];
        yim[ob + 256] = si[256];
    }
}

extern "C" void kernel_launch(void* const* d_in, const int* in_sizes, int n_in,
                              void* d_out, int out_size)
{
    const float* x = (const float*)d_in[0];
    float* out = (float*)d_out;
    float* yre = out;                                  // [32768, 257]
    float* yim = out + (long long)NBATCH * NOUT;       // [32768, 257]

    rfft512_kernel<<<NBATCH, 256>>>(x, yre, yim);
}

// round 3
// speedup vs baseline: 5.6908x; 5.6908x over previous
#include <cuda_runtime.h>
#include <math_constants.h>

#define NFFT   512
#define NOUT   257
#define NBATCH 32768
#define RPB    8          // rows (warps) per block
#define CHUNK  9          // padded chunk stride (8 data + 1 pad) -> conflict-free scatter

__device__ __forceinline__ void cmul(float ar, float ai, float br, float bi,
                                     float& cr, float& ci)
{
    cr = ar * br - ai * bi;
    ci = ar * bi + ai * br;
}

// One warp computes the 512-point RFFT of one row.
// Method: pack to z[m]=x[2m]+i x[2m+1] (m=0..255); 256-pt complex FFT as
//   256 = 8 (radix-8 in registers over reg index n2, stride 32)
//       x 32 (cross-lane DIF FFT over lane index n1, via shfl_xor),
// with the W_256^{n1*k2} twiddle in between; then the real-FFT untangle.
__global__ __launch_bounds__(256)
void rfft512_warp(const float* __restrict__ x,
                  float* __restrict__ yre,
                  float* __restrict__ yim)
{
    // Per-warp staging: Z[k] stored at addr = 9*(k>>3) + (k&7)
    __shared__ float sr[RPB][32 * CHUNK];
    __shared__ float si[RPB][32 * CHUNK];

    const int lane = threadIdx.x & 31;
    const int w    = threadIdx.x >> 5;
    const int row  = blockIdx.x * RPB + w;
    const float* xr = x + (long long)row * NFFT;

    // ---- load: z[m] = x[2m] + i x[2m+1], m = lane + 32*j (coalesced float2) ----
    float zr[8], zi[8];
    #pragma unroll
    for (int j = 0; j < 8; ++j) {
        float2 v = *reinterpret_cast<const float2*>(xr + 2 * (lane + 32 * j));
        zr[j] = v.x; zi[j] = v.y;
    }

    // ---- step A: 8-point DIF FFT over register index (n2) ----
    const float C = 0.70710678118654752440f;  // sqrt(2)/2
    {   // stage half=4 : twiddles W8^{0..3}
        float dr, di;
        dr = zr[0] - zr[4]; di = zi[0] - zi[4];
        zr[0] += zr[4]; zi[0] += zi[4];
        zr[4] = dr; zi[4] = di;

        dr = zr[1] - zr[5]; di = zi[1] - zi[5];
        zr[1] += zr[5]; zi[1] += zi[5];
        zr[5] = C * (dr + di);                 // * (c, -c)
        zi[5] = C * (di - dr);

        dr = zr[2] - zr[6]; di = zi[2] - zi[6];
        zr[2] += zr[6]; zi[2] += zi[6];
        zr[6] = di; zi[6] = -dr;               // * (0, -1)

        dr = zr[3] - zr[7]; di = zi[3] - zi[7];
        zr[3] += zr[7]; zi[3] += zi[7];
        zr[7] = C * (di - dr);                 // * (-c, -c)
        zi[7] = -C * (dr + di);
    }
    {   // stage half=2 : twiddles 1, -i
        float dr, di;
        dr = zr[0] - zr[2]; di = zi[0] - zi[2];
        zr[0] += zr[2]; zi[0] += zi[2]; zr[2] = dr; zi[2] = di;

        dr = zr[1] - zr[3]; di = zi[1] - zi[3];
        zr[1] += zr[3]; zi[1] += zi[3]; zr[3] = di; zi[3] = -dr;

        dr = zr[4] - zr[6]; di = zi[4] - zi[6];
        zr[4] += zr[6]; zi[4] += zi[6]; zr[6] = dr; zi[6] = di;

        dr = zr[5] - zr[7]; di = zi[5] - zi[7];
        zr[5] += zr[7]; zi[5] += zi[7]; zr[7] = di; zi[7] = -dr;
    }
    {   // stage half=1
        float dr, di;
        dr = zr[0] - zr[1]; di = zi[0] - zi[1];
        zr[0] += zr[1]; zi[0] += zi[1]; zr[1] = dr; zi[1] = di;
        dr = zr[2] - zr[3]; di = zi[2] - zi[3];
        zr[2] += zr[3]; zi[2] += zi[3]; zr[3] = dr; zi[3] = di;
        dr = zr[4] - zr[5]; di = zi[4] - zi[5];
        zr[4] += zr[5]; zi[4] += zi[5]; zr[5] = dr; zi[5] = di;
        dr = zr[6] - zr[7]; di = zi[6] - zi[7];
        zr[6] += zr[7]; zi[6] += zi[7]; zr[7] = dr; zi[7] = di;
    }
    // slot r now holds k2 = {0,4,2,6,1,5,3,7}[r] (DIF bit-reversed order)

    // ---- step B: multiply slot (k2) by W_256^{lane * k2} ----
    {
        float w1r, w1i;
        __sincosf(-2.0f * CUDART_PI_F * (float)lane / 256.0f, &w1i, &w1r);
        float w2r, w2i, w3r, w3i, w4r, w4i, w5r, w5i, w6r, w6i, w7r, w7i;
        cmul(w1r, w1i, w1r, w1i, w2r, w2i);
        cmul(w2r, w2i, w1r, w1i, w3r, w3i);
        cmul(w2r, w2i, w2r, w2i, w4r, w4i);
        cmul(w4r, w4i, w1r, w1i, w5r, w5i);
        cmul(w3r, w3i, w3r, w3i, w6r, w6i);
        cmul(w4r, w4i, w3r, w3i, w7r, w7i);

        float tr, ti;
        cmul(zr[1], zi[1], w4r, w4i, tr, ti); zr[1] = tr; zi[1] = ti;  // k2=4
        cmul(zr[2], zi[2], w2r, w2i, tr, ti); zr[2] = tr; zi[2] = ti;  // k2=2
        cmul(zr[3], zi[3], w6r, w6i, tr, ti); zr[3] = tr; zi[3] = ti;  // k2=6
        cmul(zr[4], zi[4], w1r, w1i, tr, ti); zr[4] = tr; zi[4] = ti;  // k2=1
        cmul(zr[5], zi[5], w5r, w5i, tr, ti); zr[5] = tr; zi[5] = ti;  // k2=5
        cmul(zr[6], zi[6], w3r, w3i, tr, ti); zr[6] = tr; zi[6] = ti;  // k2=3
        cmul(zr[7], zi[7], w7r, w7i, tr, ti); zr[7] = tr; zi[7] = ti;  // k2=7
    }

    // ---- step C: 32-point DIF FFT across lanes (per register slot) ----
    #pragma unroll
    for (int s = 0; s < 5; ++s) {
        const int h = 16 >> s;                 // butterfly distance
        float tc, ts;
        if (h > 1) {
            float ang = -CUDART_PI_F * (float)(lane & (h - 1)) / (float)h;
            __sincosf(ang, &ts, &tc);
        } else { tc = 1.0f; ts = 0.0f; }
        const bool hi = (lane & h) != 0;
        #pragma unroll
        for (int r = 0; r < 8; ++r) {
            float orr = __shfl_xor_sync(0xffffffffu, zr[r], h);
            float oii = __shfl_xor_sync(0xffffffffu, zi[r], h);
            if (hi) {
                float dr = orr - zr[r], di = oii - zi[r];
                zr[r] = dr * tc - di * ts;
                zi[r] = dr * ts + di * tc;
            } else {
                zr[r] += orr;
                zi[r] += oii;
            }
        }
    }
    // lane l, slot r now holds Z[k2[r] + 8*bitrev5(l)]

    // ---- scatter Z to shared (conflict-free: addr = 9*k1 + k2) ----
    {
        const int p5 = __brev((unsigned)lane) >> 27;       // bitrev5(lane)
        const int base = CHUNK * p5;
        const int k2m[8] = {0, 4, 2, 6, 1, 5, 3, 7};
        #pragma unroll
        for (int r = 0; r < 8; ++r) {
            sr[w][base + k2m[r]] = zr[r];
            si[w][base + k2m[r]] = zi[r];
        }
    }
    __syncwarp();

    // ---- untangle + store: X[k] = Fe + W_512^k * Fo, k = 32j + lane ----
    float* orow = yre + (long long)row * NOUT;
    float* irow = yim + (long long)row * NOUT;
    {
        #pragma unroll
        for (int j = 0; j < 8; ++j) {
            const int k  = 32 * j + lane;
            const int km = (256 - k) & 255;
            const float Zr = sr[w][CHUNK * (k  >> 3) + (k  & 7)];
            const float Zi = si[w][CHUNK * (k  >> 3) + (k  & 7)];
            const float Mr = sr[w][CHUNK * (km >> 3) + (km & 7)];
            const float Mi = si[w][CHUNK * (km >> 3) + (km & 7)];

            const float Fer = 0.5f * (Zr + Mr);
            const float Fei = 0.5f * (Zi - Mi);
            const float For = 0.5f * (Zi + Mi);
            const float Foi = -0.5f * (Zr - Mr);

            // W_512^k computed directly (recurrence constant was the R2 bug)
            float wc, ws;
            __sincosf(-2.0f * CUDART_PI_F * (float)k / 512.0f, &ws, &wc);

            orow[k] = Fer + wc * For - ws * Foi;
            irow[k] = Fei + wc * Foi + ws * For;
        }
        if (lane == 0) {
            const float Z0r = sr[w][0], Z0i = si[w][0];
            orow[256] = Z0r - Z0i;
            irow[256] = 0.0f;
        }
    }
}

extern "C" void kernel_launch(void* const* d_in, const int* in_sizes, int n_in,
                              void* d_out, int out_size)
{
    const float* x = (const float*)d_in[0];
    float* out = (float*)d_out;
    float* yre = out;                                  // [32768, 257]
    float* yim = out + (long long)NBATCH * NOUT;       // [32768, 257]

    rfft512_warp<<<NBATCH / RPB, 32 * RPB>>>(x, yre, yim);
}

// round 4
// speedup vs baseline: 6.1299x; 1.0771x over previous
#include <cuda_runtime.h>
#include <math_constants.h>

#define NOUT   257
#define NBATCH 32768
#define RPB    8

__device__ __forceinline__ void cmul(float ar, float ai, float br, float bi,
                                     float& cr, float& ci)
{
    cr = ar * br - ai * bi;
    ci = ar * bi + ai * br;
}

// Cross-lane DIT stage (butterfly distance H). Folded per-lane coefficient
// (wcs,wss) already includes both the twiddle-index correction and the
// hi-lane negation (they cancel for H=2,4,8; explicit for H=16).
template<int H>
__device__ __forceinline__ void dit_stage(float* zr, float* zi,
                                          float wcs, float wss, int lane)
{
    const bool hi = (lane & H) != 0;
    #pragma unroll
    for (int r = 0; r < 8; ++r) {
        const float orr = __shfl_xor_sync(0xffffffffu, zr[r], H);
        const float oii = __shfl_xor_sync(0xffffffffu, zi[r], H);
        const float amr = hi ? zr[r] : orr;   // value that gets twiddled: a[i1]
        const float ami = hi ? zi[r] : oii;
        const float bsr = hi ? orr : zr[r];   // base: a[i0]
        const float bsi = hi ? oii : zi[r];
        zr[r] = fmaf(wcs, amr, fmaf(-wss, ami, bsr));
        zi[r] = fmaf(wcs, ami, fmaf( wss, amr, bsi));
    }
}

__global__ __launch_bounds__(256)
void rfft512_warp(const float* __restrict__ x,
                  float* __restrict__ yre,
                  float* __restrict__ yim)
{
    // Staging for coalesced stores: X[8l+d] at idx 36d+l (conflict-free both ways)
    __shared__ float sxr[RPB][288];
    __shared__ float sxi[RPB][288];

    const int lane = threadIdx.x & 31;
    const int w    = threadIdx.x >> 5;
    const long long row = (long long)blockIdx.x * RPB + w;
    const float* xr = x + row * 512;

    const int n1 = __brev((unsigned)lane) >> 27;   // bitrev5(lane)

    // ---- load z[m] = 0.5*(x[2m] + i x[2m+1]), m = n1 + 32 r (coalesced) ----
    float zr[8], zi[8];
    #pragma unroll
    for (int r = 0; r < 8; ++r) {
        float2 v = *reinterpret_cast<const float2*>(xr + 2 * (n1 + 32 * r));
        zr[r] = 0.5f * v.x; zi[r] = 0.5f * v.y;
    }

    // ---- step A: radix-8 DIF over reg index -> slot r holds k2 = bitrev3(r) ----
    const float C = 0.70710678118654752440f;
    {   // h=4, twiddles W8^{0..3}
        float dr, di;
        dr = zr[0] - zr[4]; di = zi[0] - zi[4];
        zr[0] += zr[4]; zi[0] += zi[4];
        zr[4] = dr; zi[4] = di;

        dr = zr[1] - zr[5]; di = zi[1] - zi[5];
        zr[1] += zr[5]; zi[1] += zi[5];
        zr[5] = C * (dr + di); zi[5] = C * (di - dr);

        dr = zr[2] - zr[6]; di = zi[2] - zi[6];
        zr[2] += zr[6]; zi[2] += zi[6];
        zr[6] = di; zi[6] = -dr;

        dr = zr[3] - zr[7]; di = zi[3] - zi[7];
        zr[3] += zr[7]; zi[3] += zi[7];
        zr[7] = C * (di - dr); zi[7] = -C * (dr + di);
    }
    {   // h=2, twiddles 1, -i
        float dr, di;
        dr = zr[0] - zr[2]; di = zi[0] - zi[2];
        zr[0] += zr[2]; zi[0] += zi[2]; zr[2] = dr; zi[2] = di;

        dr = zr[1] - zr[3]; di = zi[1] - zi[3];
        zr[1] += zr[3]; zi[1] += zi[3]; zr[3] = di; zi[3] = -dr;

        dr = zr[4] - zr[6]; di = zi[4] - zi[6];
        zr[4] += zr[6]; zi[4] += zi[6]; zr[6] = dr; zi[6] = di;

        dr = zr[5] - zr[7]; di = zi[5] - zi[7];
        zr[5] += zr[7]; zi[5] += zi[7]; zr[7] = di; zi[7] = -dr;
    }
    {   // h=1
        float dr, di;
        dr = zr[0] - zr[1]; di = zi[0] - zi[1];
        zr[0] += zr[1]; zi[0] += zi[1]; zr[1] = dr; zi[1] = di;
        dr = zr[2] - zr[3]; di = zi[2] - zi[3];
        zr[2] += zr[3]; zi[2] += zi[3]; zr[3] = dr; zi[3] = di;
        dr = zr[4] - zr[5]; di = zi[4] - zi[5];
        zr[4] += zr[5]; zi[4] += zi[5]; zr[5] = dr; zi[5] = di;
        dr = zr[6] - zr[7]; di = zi[6] - zi[7];
        zr[6] += zr[7]; zi[6] += zi[7]; zr[7] = dr; zi[7] = di;
    }

    // ---- step B: multiply slot (k2) by W_256^{n1*k2} ----
    {
        float w1r, w1i;
        __sincosf(-2.0f * CUDART_PI_F * (float)n1 / 256.0f, &w1i, &w1r);
        float w2r, w2i, w3r, w3i, w4r, w4i, w5r, w5i, w6r, w6i, w7r, w7i;
        cmul(w1r, w1i, w1r, w1i, w2r, w2i);
        cmul(w2r, w2i, w1r, w1i, w3r, w3i);
        cmul(w2r, w2i, w2r, w2i, w4r, w4i);
        cmul(w4r, w4i, w1r, w1i, w5r, w5i);
        cmul(w3r, w3i, w3r, w3i, w6r, w6i);
        cmul(w4r, w4i, w3r, w3i, w7r, w7i);

        float tr, ti;
        cmul(zr[1], zi[1], w4r, w4i, tr, ti); zr[1] = tr; zi[1] = ti;  // k2=4
        cmul(zr[2], zi[2], w2r, w2i, tr, ti); zr[2] = tr; zi[2] = ti;  // k2=2
        cmul(zr[3], zi[3], w6r, w6i, tr, ti); zr[3] = tr; zi[3] = ti;  // k2=6
        cmul(zr[4], zi[4], w1r, w1i, tr, ti); zr[4] = tr; zi[4] = ti;  // k2=1
        cmul(zr[5], zi[5], w5r, w5i, tr, ti); zr[5] = tr; zi[5] = ti;  // k2=5
        cmul(zr[6], zi[6], w3r, w3i, tr, ti); zr[6] = tr; zi[6] = ti;  // k2=3
        cmul(zr[7], zi[7], w7r, w7i, tr, ti); zr[7] = tr; zi[7] = ti;  // k2=7
    }

    // ---- step C: 32-pt DIT across lanes (input at bitrev lanes -> natural out) ----
    {
        // One sincosf; all stage coefficients by squaring. Sign corrections
        // cancel against the hi-lane butterfly negation for h=2,4,8.
        float uc, us;
        __sincosf(-CUDART_PI_F * (float)(lane & 15) / 16.0f, &us, &uc);
        const float p2c = uc * uc - us * us, p2s = 2.0f * uc * us;
        const float p4c = p2c * p2c - p2s * p2s, p4s = 2.0f * p2c * p2s;
        const float p8c = p4c * p4c - p4s * p4s, p8s = 2.0f * p4c * p4s;

        // h=1: W=1, res = other + s*z
        {
            const float s1 = (lane & 1) ? -1.0f : 1.0f;
            #pragma unroll
            for (int r = 0; r < 8; ++r) {
                const float orr = __shfl_xor_sync(0xffffffffu, zr[r], 1);
                const float oii = __shfl_xor_sync(0xffffffffu, zi[r], 1);
                zr[r] = fmaf(s1, zr[r], orr);
                zi[r] = fmaf(s1, zi[r], oii);
            }
        }
        dit_stage<2>(zr, zi, p8c, p8s, lane);
        dit_stage<4>(zr, zi, p4c, p4s, lane);
        dit_stage<8>(zr, zi, p2c, p2s, lane);
        const float w16c = (lane & 16) ? -uc : uc;
        const float w16s = (lane & 16) ? -us : us;
        dit_stage<16>(zr, zi, w16c, w16s, lane);
    }
    // lane l, slot r now holds 0.5 * Z[k2m[r] + 8*l],  k2m = {0,4,2,6,1,5,3,7}

    // ---- untangle X[k] = Fe + W_512^k Fo for k = 8*lane + d, via shuffles ----
    {
        float bc, bs;   // W_64^lane = exp(-i pi lane / 32)
        __sincosf(-CUDART_PI_F * (float)lane / 32.0f, &bs, &bc);

        // Cd = exp(-i pi d / 256) = (cd, -sd)
        const float CDC[8] = {1.0f, 0.99992470183914454f, 0.99969881869620420f,
                              0.99932238458834950f, 0.99879545620517240f,
                              0.99811811290014920f, 0.99729045667869020f,
                              0.99631261218277800f};
        const float CDS[8] = {0.0f, 0.012271538285719925f, 0.024541228522912288f,
                              0.036807222941358832f, 0.049067674327418015f,
                              0.061320736302208578f, 0.073564563599667426f,
                              0.085797312344439894f};
        const int IZ[8] = {0, 4, 2, 6, 1, 5, 3, 7};   // slot holding k2 = d
        const int SM[8] = {0, 7, 3, 5, 1, 6, 2, 4};   // slot holding k2 = 8-d

        #pragma unroll
        for (int d = 0; d < 8; ++d) {
            const float zkr = zr[IZ[d]], zki = zi[IZ[d]];
            float zmr, zmi;
            if (d == 0) {
                const int src = (32 - lane) & 31;
                zmr = __shfl_sync(0xffffffffu, zr[0], src);
                zmi = __shfl_sync(0xffffffffu, zi[0], src);
            } else {
                zmr = __shfl_xor_sync(0xffffffffu, zr[SM[d]], 31);
                zmi = __shfl_xor_sync(0xffffffffu, zi[SM[d]], 31);
            }
            // W_512^{8l+d} = (bc + i bs)(cd - i sd)
            const float wc = (d == 0) ? bc : fmaf(bc, CDC[d],  bs * CDS[d]);
            const float ws = (d == 0) ? bs : fmaf(bs, CDC[d], -bc * CDS[d]);

            const float Fer = zkr + zmr;
            const float Fei = zki - zmi;
            const float For = zki + zmi;
            const float Foi = zmr - zkr;

            sxr[w][36 * d + lane] = fmaf(wc, For, fmaf(-ws, Foi, Fer));
            sxi[w][36 * d + lane] = fmaf(wc, Foi, fmaf( ws, For, Fei));
        }
    }

    float* orow = yre + row * NOUT;
    float* irow = yim + row * NOUT;

    if (lane == 0) {   // bin 256: X[256] = Re(Z0) - Im(Z0); z holds 0.5*Z
        orow[256] = 2.0f * (zr[0] - zi[0]);
        irow[256] = 0.0f;
    }
    __syncwarp();

    // ---- coalesced stores: X[32j + lane] from idx 36*(lane&7) + 4j + (lane>>3) ----
    #pragma unroll
    for (int j = 0; j < 8; ++j) {
        const int idx = 36 * (lane & 7) + 4 * j + (lane >> 3);
        const int k   = 32 * j + lane;
        orow[k] = sxr[w][idx];
        irow[k] = sxi[w][idx];
    }
}

extern "C" void kernel_launch(void* const* d_in, const int* in_sizes, int n_in,
                              void* d_out, int out_size)
{
    const float* x = (const float*)d_in[0];
    float* out = (float*)d_out;
    float* yre = out;                                  // [32768, 257]
    float* yim = out + (long long)NBATCH * NOUT;       // [32768, 257]

    rfft512_warp<<<NBATCH / RPB, 32 * RPB>>>(x, yre, yim);
}

// round 5
// speedup vs baseline: 6.4314x; 1.0492x over previous
#include <cuda_runtime.h>
#include <math_constants.h>

#define NOUT   257
#define NBATCH 32768
#define RPB    8

__device__ __forceinline__ void cmul(float ar, float ai, float br, float bi,
                                     float& cr, float& ci)
{
    cr = ar * br - ai * bi;
    ci = ar * bi + ai * br;
}

// Cross-lane DIF stage, butterfly distance H.
// Lo lane (bit H clear): out = mine + other            (s=+1, w=(1,0))
// Hi lane (bit H set):   out = (other - mine) * w      (s=-1, w=stage coeff)
// No selects in the loop: s/wc/ws are hoisted per stage.
template<int H>
__device__ __forceinline__ void dif_stage(float* zr, float* zi,
                                          float s, float wc, float ws)
{
    #pragma unroll
    for (int r = 0; r < 8; ++r) {
        const float orr = __shfl_xor_sync(0xffffffffu, zr[r], H);
        const float oii = __shfl_xor_sync(0xffffffffu, zi[r], H);
        const float dr = fmaf(s, zr[r], orr);
        const float di = fmaf(s, zi[r], oii);
        zr[r] = fmaf(wc, dr, -ws * di);
        zi[r] = fmaf(wc, di,  ws * dr);
    }
}

__global__ __launch_bounds__(256)
void rfft512_warp(const float* __restrict__ x,
                  float* __restrict__ yre,
                  float* __restrict__ yim)
{
    // Staging for coalesced stores: X[8*kappa+d] at idx 36d+kappa (conflict-free)
    __shared__ float sxr[RPB][288];
    __shared__ float sxi[RPB][288];

    const int lane = threadIdx.x & 31;
    const int w    = threadIdx.x >> 5;
    const long long row = (long long)blockIdx.x * RPB + w;
    const float* xr = x + row * 512;

    // ---- load z[m] = 0.5*(x[2m] + i x[2m+1]), m = lane + 32 r (natural order) ----
    float zr[8], zi[8];
    #pragma unroll
    for (int r = 0; r < 8; ++r) {
        float2 v = *reinterpret_cast<const float2*>(xr + 2 * (lane + 32 * r));
        zr[r] = 0.5f * v.x; zi[r] = 0.5f * v.y;
    }

    // ---- step A: radix-8 DIF over reg index -> slot r holds k2 = bitrev3(r) ----
    const float C = 0.70710678118654752440f;
    {   // h=4, twiddles W8^{0..3}
        float dr, di;
        dr = zr[0] - zr[4]; di = zi[0] - zi[4];
        zr[0] += zr[4]; zi[0] += zi[4];
        zr[4] = dr; zi[4] = di;

        dr = zr[1] - zr[5]; di = zi[1] - zi[5];
        zr[1] += zr[5]; zi[1] += zi[5];
        zr[5] = C * (dr + di); zi[5] = C * (di - dr);

        dr = zr[2] - zr[6]; di = zi[2] - zi[6];
        zr[2] += zr[6]; zi[2] += zi[6];
        zr[6] = di; zi[6] = -dr;

        dr = zr[3] - zr[7]; di = zi[3] - zi[7];
        zr[3] += zr[7]; zi[3] += zi[7];
        zr[7] = C * (di - dr); zi[7] = -C * (dr + di);
    }
    {   // h=2, twiddles 1, -i
        float dr, di;
        dr = zr[0] - zr[2]; di = zi[0] - zi[2];
        zr[0] += zr[2]; zi[0] += zi[2]; zr[2] = dr; zi[2] = di;

        dr = zr[1] - zr[3]; di = zi[1] - zi[3];
        zr[1] += zr[3]; zi[1] += zi[3]; zr[3] = di; zi[3] = -dr;

        dr = zr[4] - zr[6]; di = zi[4] - zi[6];
        zr[4] += zr[6]; zi[4] += zi[6]; zr[6] = dr; zi[6] = di;

        dr = zr[5] - zr[7]; di = zi[5] - zi[7];
        zr[5] += zr[7]; zi[5] += zi[7]; zr[7] = di; zi[7] = -dr;
    }
    {   // h=1
        float dr, di;
        dr = zr[0] - zr[1]; di = zi[0] - zi[1];
        zr[0] += zr[1]; zi[0] += zi[1]; zr[1] = dr; zi[1] = di;
        dr = zr[2] - zr[3]; di = zi[2] - zi[3];
        zr[2] += zr[3]; zi[2] += zi[3]; zr[3] = dr; zi[3] = di;
        dr = zr[4] - zr[5]; di = zi[4] - zi[5];
        zr[4] += zr[5]; zi[4] += zi[5]; zr[5] = dr; zi[5] = di;
        dr = zr[6] - zr[7]; di = zi[6] - zi[7];
        zr[6] += zr[7]; zi[6] += zi[7]; zr[7] = dr; zi[7] = di;
    }

    // ---- step B: multiply slot (k2) by W_256^{lane * k2} ----
    {
        float w1r, w1i;
        __sincosf(-2.0f * CUDART_PI_F * (float)lane / 256.0f, &w1i, &w1r);
        float w2r, w2i, w3r, w3i, w4r, w4i, w5r, w5i, w6r, w6i, w7r, w7i;
        cmul(w1r, w1i, w1r, w1i, w2r, w2i);
        cmul(w2r, w2i, w1r, w1i, w3r, w3i);
        cmul(w2r, w2i, w2r, w2i, w4r, w4i);
        cmul(w4r, w4i, w1r, w1i, w5r, w5i);
        cmul(w3r, w3i, w3r, w3i, w6r, w6i);
        cmul(w4r, w4i, w3r, w3i, w7r, w7i);

        float tr, ti;
        cmul(zr[1], zi[1], w4r, w4i, tr, ti); zr[1] = tr; zi[1] = ti;  // k2=4
        cmul(zr[2], zi[2], w2r, w2i, tr, ti); zr[2] = tr; zi[2] = ti;  // k2=2
        cmul(zr[3], zi[3], w6r, w6i, tr, ti); zr[3] = tr; zi[3] = ti;  // k2=6
        cmul(zr[4], zi[4], w1r, w1i, tr, ti); zr[4] = tr; zi[4] = ti;  // k2=1
        cmul(zr[5], zi[5], w5r, w5i, tr, ti); zr[5] = tr; zi[5] = ti;  // k2=5
        cmul(zr[6], zi[6], w3r, w3i, tr, ti); zr[6] = tr; zi[6] = ti;  // k2=3
        cmul(zr[7], zi[7], w7r, w7i, tr, ti); zr[7] = tr; zi[7] = ti;  // k2=7
    }

    // ---- step C: 32-pt DIF across lanes; output k1 = bitrev5(lane) ----
    {
        // u = W_32^{lane&15}; all stage coefficients by squaring.
        // On applying (hi) lanes the exponent-masking sign is uniformly -1.
        float uc, us;
        __sincosf(-CUDART_PI_F * (float)(lane & 15) / 16.0f, &us, &uc);
        const float p2c = uc * uc - us * us,     p2s = 2.0f * uc * us;
        const float p4c = p2c * p2c - p2s * p2s, p4s = 2.0f * p2c * p2s;
        const float p8c = p4c * p4c - p4s * p4s, p8s = 2.0f * p4c * p4s;

        {   // H=16: w = u
            const bool hi = (lane & 16) != 0;
            dif_stage<16>(zr, zi, hi ? -1.0f : 1.0f,
                          hi ? uc : 1.0f, hi ? us : 0.0f);
        }
        {   // H=8: w = -u^2
            const bool hi = (lane & 8) != 0;
            dif_stage<8>(zr, zi, hi ? -1.0f : 1.0f,
                         hi ? -p2c : 1.0f, hi ? -p2s : 0.0f);
        }
        {   // H=4: w = -u^4
            const bool hi = (lane & 4) != 0;
            dif_stage<4>(zr, zi, hi ? -1.0f : 1.0f,
                         hi ? -p4c : 1.0f, hi ? -p4s : 0.0f);
        }
        {   // H=2: w = -u^8
            const bool hi = (lane & 2) != 0;
            dif_stage<2>(zr, zi, hi ? -1.0f : 1.0f,
                         hi ? -p8c : 1.0f, hi ? -p8s : 0.0f);
        }
        {   // H=1: w = 1 (twiddle-free)
            const float s1 = (lane & 1) ? -1.0f : 1.0f;
            #pragma unroll
            for (int r = 0; r < 8; ++r) {
                const float orr = __shfl_xor_sync(0xffffffffu, zr[r], 1);
                const float oii = __shfl_xor_sync(0xffffffffu, zi[r], 1);
                zr[r] = fmaf(s1, zr[r], orr);
                zi[r] = fmaf(s1, zi[r], oii);
            }
        }
    }
    // lane l, slot r now holds 0.5 * Z[k2 + 8*kappa], k2 = br3(r), kappa = br5(l)

    const int kap = __brev((unsigned)lane) >> 27;   // bitrev5(lane)

    // ---- untangle X[k] = Fe + W_512^k Fo for k = 8*kappa + d, via shuffles ----
    {
        float bc, bs;   // W_64^kappa = exp(-i pi kappa / 32)
        __sincosf(-CUDART_PI_F * (float)kap / 32.0f, &bs, &bc);

        // Cd = exp(-i pi d / 256) = (cd, -sd)
        const float CDC[8] = {1.0f, 0.99992470183914454f, 0.99969881869620420f,
                              0.99932238458834950f, 0.99879545620517240f,
                              0.99811811290014920f, 0.99729045667869020f,
                              0.99631261218277800f};
        const float CDS[8] = {0.0f, 0.012271538285719925f, 0.024541228522912288f,
                              0.036807222941358832f, 0.049067674327418015f,
                              0.061320736302208578f, 0.073564563599667426f,
                              0.085797312344439894f};
        const int IZ[8] = {0, 4, 2, 6, 1, 5, 3, 7};   // slot holding k2 = d
        const int SM[8] = {0, 7, 3, 5, 1, 6, 2, 4};   // slot holding k2 = 8-d

        // d=0 partner: kappa' = (32-kappa)&31 lives on lane br5(kappa')
        const int src0 = __brev((unsigned)((32 - kap) & 31)) >> 27;

        #pragma unroll
        for (int d = 0; d < 8; ++d) {
            const float zkr = zr[IZ[d]], zki = zi[IZ[d]];
            float zmr, zmi;
            if (d == 0) {
                zmr = __shfl_sync(0xffffffffu, zr[0], src0);
                zmi = __shfl_sync(0xffffffffu, zi[0], src0);
            } else {
                zmr = __shfl_xor_sync(0xffffffffu, zr[SM[d]], 31);
                zmi = __shfl_xor_sync(0xffffffffu, zi[SM[d]], 31);
            }
            // W_512^{8kappa+d} = (bc + i bs)(cd - i sd)
            const float wc = (d == 0) ? bc : fmaf(bc, CDC[d],  bs * CDS[d]);
            const float ws = (d == 0) ? bs : fmaf(bs, CDC[d], -bc * CDS[d]);

            const float Fer = zkr + zmr;
            const float Fei = zki - zmi;
            const float For = zki + zmi;
            const float Foi = zmr - zkr;

            sxr[w][36 * d + kap] = fmaf(wc, For, fmaf(-ws, Foi, Fer));
            sxi[w][36 * d + kap] = fmaf(wc, Foi, fmaf( ws, For, Fei));
        }
    }

    float* orow = yre + row * NOUT;
    float* irow = yim + row * NOUT;

    if (lane == 0) {   // bin 256: X[256] = Re(Z0) - Im(Z0); z holds 0.5*Z
        orow[256] = 2.0f * (zr[0] - zi[0]);
        irow[256] = 0.0f;
    }
    __syncwarp();

    // ---- coalesced stores: X[32j + lane] from idx 36*(lane&7) + 4j + (lane>>3) ----
    #pragma unroll
    for (int j = 0; j < 8; ++j) {
        const int idx = 36 * (lane & 7) + 4 * j + (lane >> 3);
        const int k   = 32 * j + lane;
        orow[k] = sxr[w][idx];
        irow[k] = sxi[w][idx];
    }
}

extern "C" void kernel_launch(void* const* d_in, const int* in_sizes, int n_in,
                              void* d_out, int out_size)
{
    const float* x = (const float*)d_in[0];
    float* out = (float*)d_out;
    float* yre = out;                                  // [32768, 257]
    float* yim = out + (long long)NBATCH * NOUT;       // [32768, 257]

    rfft512_warp<<<NBATCH / RPB, 32 * RPB>>>(x, yre, yim);
}

// round 6
// speedup vs baseline: 6.9978x; 1.0881x over previous
#include <cuda_runtime.h>
#include <math_constants.h>
#include <cstdint>

#define NOUT   257
#define NBATCH 32768
#define RPB    8

__device__ __forceinline__ void cmul(float ar, float ai, float br, float bi,
                                     float& cr, float& ci)
{
    cr = ar * br - ai * bi;
    ci = ar * bi + ai * br;
}

// ---- f32x2 packed helpers (sm_103a native) ----
__device__ __forceinline__ uint64_t pk2(float lo, float hi) {
    uint64_t r;
    asm("mov.b64 %0, {%1, %2};" : "=l"(r) : "f"(lo), "f"(hi));
    return r;
}
__device__ __forceinline__ void upk2(uint64_t v, float& lo, float& hi) {
    asm("mov.b64 {%0, %1}, %2;" : "=f"(lo), "=f"(hi) : "l"(v));
}
__device__ __forceinline__ uint64_t fma2(uint64_t a, uint64_t b, uint64_t c) {
    uint64_t d;
    asm("fma.rn.f32x2 %0, %1, %2, %3;" : "=l"(d) : "l"(a), "l"(b), "l"(c));
    return d;
}
__device__ __forceinline__ uint64_t mul2(uint64_t a, uint64_t b) {
    uint64_t d;
    asm("mul.rn.f32x2 %0, %1, %2;" : "=l"(d) : "l"(a), "l"(b));
    return d;
}

#define ONE2  0x3F8000003F800000ull   // ( 1.0f,  1.0f)
#define NEG2  0xBF800000BF800000ull   // (-1.0f, -1.0f)

// Packed cross-lane DIF stage, butterfly distance H.
// Lo lane: out = mine + other; Hi lane: out = (other - mine) * w.
// All 4 packed reg-pairs share the same per-lane coefficients.
template<int H>
__device__ __forceinline__ void dif_stage_p(uint64_t* Zr, uint64_t* Zi,
                                            uint64_t s2, uint64_t wc2,
                                            uint64_t nws2, uint64_t ws2)
{
    #pragma unroll
    for (int q = 0; q < 4; ++q) {
        const uint64_t orr = __shfl_xor_sync(0xffffffffu, Zr[q], H);
        const uint64_t oii = __shfl_xor_sync(0xffffffffu, Zi[q], H);
        const uint64_t dr = fma2(s2, Zr[q], orr);
        const uint64_t di = fma2(s2, Zi[q], oii);
        Zr[q] = fma2(wc2, dr, mul2(nws2, di));
        Zi[q] = fma2(wc2, di, mul2(ws2,  dr));
    }
}

__global__ __launch_bounds__(256)
void rfft512_warp(const float* __restrict__ x,
                  float* __restrict__ yre,
                  float* __restrict__ yim)
{
    // Staging for coalesced stores: X[8*kappa+d] at idx 36d+kappa (conflict-free)
    __shared__ float sxr[RPB][288];
    __shared__ float sxi[RPB][288];

    const int lane = threadIdx.x & 31;
    const int w    = threadIdx.x >> 5;
    const long long row = (long long)blockIdx.x * RPB + w;
    const float* xr = x + row * 512;

    // ---- load z[m] = 0.5*(x[2m] + i x[2m+1]), m = lane + 32 r ----
    float zr[8], zi[8];
    #pragma unroll
    for (int r = 0; r < 8; ++r) {
        float2 v = *reinterpret_cast<const float2*>(xr + 2 * (lane + 32 * r));
        zr[r] = 0.5f * v.x; zi[r] = 0.5f * v.y;
    }

    // ---- step A: radix-8 DIF over reg index -> slot r holds k2 = bitrev3(r) ----
    const float C = 0.70710678118654752440f;
    {   // h=4, twiddles W8^{0..3}
        float dr, di;
        dr = zr[0] - zr[4]; di = zi[0] - zi[4];
        zr[0] += zr[4]; zi[0] += zi[4];
        zr[4] = dr; zi[4] = di;

        dr = zr[1] - zr[5]; di = zi[1] - zi[5];
        zr[1] += zr[5]; zi[1] += zi[5];
        zr[5] = C * (dr + di); zi[5] = C * (di - dr);

        dr = zr[2] - zr[6]; di = zi[2] - zi[6];
        zr[2] += zr[6]; zi[2] += zi[6];
        zr[6] = di; zi[6] = -dr;

        dr = zr[3] - zr[7]; di = zi[3] - zi[7];
        zr[3] += zr[7]; zi[3] += zi[7];
        zr[7] = C * (di - dr); zi[7] = -C * (dr + di);
    }
    {   // h=2, twiddles 1, -i
        float dr, di;
        dr = zr[0] - zr[2]; di = zi[0] - zi[2];
        zr[0] += zr[2]; zi[0] += zi[2]; zr[2] = dr; zi[2] = di;

        dr = zr[1] - zr[3]; di = zi[1] - zi[3];
        zr[1] += zr[3]; zi[1] += zi[3]; zr[3] = di; zi[3] = -dr;

        dr = zr[4] - zr[6]; di = zi[4] - zi[6];
        zr[4] += zr[6]; zi[4] += zi[6]; zr[6] = dr; zi[6] = di;

        dr = zr[5] - zr[7]; di = zi[5] - zi[7];
        zr[5] += zr[7]; zi[5] += zi[7]; zr[7] = di; zi[7] = -dr;
    }
    {   // h=1
        float dr, di;
        dr = zr[0] - zr[1]; di = zi[0] - zi[1];
        zr[0] += zr[1]; zi[0] += zi[1]; zr[1] = dr; zi[1] = di;
        dr = zr[2] - zr[3]; di = zi[2] - zi[3];
        zr[2] += zr[3]; zi[2] += zi[3]; zr[3] = dr; zi[3] = di;
        dr = zr[4] - zr[5]; di = zi[4] - zi[5];
        zr[4] += zr[5]; zi[4] += zi[5]; zr[5] = dr; zi[5] = di;
        dr = zr[6] - zr[7]; di = zi[6] - zi[7];
        zr[6] += zr[7]; zi[6] += zi[7]; zr[7] = dr; zi[7] = di;
    }

    // ---- step B: multiply slot (k2) by W_256^{lane * k2} ----
    {
        float w1r, w1i;
        __sincosf(-2.0f * CUDART_PI_F * (float)lane / 256.0f, &w1i, &w1r);
        float w2r, w2i, w3r, w3i, w4r, w4i, w5r, w5i, w6r, w6i, w7r, w7i;
        cmul(w1r, w1i, w1r, w1i, w2r, w2i);
        cmul(w2r, w2i, w1r, w1i, w3r, w3i);
        cmul(w2r, w2i, w2r, w2i, w4r, w4i);
        cmul(w4r, w4i, w1r, w1i, w5r, w5i);
        cmul(w3r, w3i, w3r, w3i, w6r, w6i);
        cmul(w4r, w4i, w3r, w3i, w7r, w7i);

        float tr, ti;
        cmul(zr[1], zi[1], w4r, w4i, tr, ti); zr[1] = tr; zi[1] = ti;  // k2=4
        cmul(zr[2], zi[2], w2r, w2i, tr, ti); zr[2] = tr; zi[2] = ti;  // k2=2
        cmul(zr[3], zi[3], w6r, w6i, tr, ti); zr[3] = tr; zi[3] = ti;  // k2=6
        cmul(zr[4], zi[4], w1r, w1i, tr, ti); zr[4] = tr; zi[4] = ti;  // k2=1
        cmul(zr[5], zi[5], w5r, w5i, tr, ti); zr[5] = tr; zi[5] = ti;  // k2=5
        cmul(zr[6], zi[6], w3r, w3i, tr, ti); zr[6] = tr; zi[6] = ti;  // k2=3
        cmul(zr[7], zi[7], w7r, w7i, tr, ti); zr[7] = tr; zi[7] = ti;  // k2=7
    }

    // ---- step C: 32-pt DIF across lanes, f32x2-packed over reg pairs ----
    {
        float uc, us;   // u = W_32^{lane&15}
        __sincosf(-CUDART_PI_F * (float)(lane & 15) / 16.0f, &us, &uc);
        const float p2c = uc * uc - us * us,     p2s = 2.0f * uc * us;
        const float p4c = p2c * p2c - p2s * p2s, p4s = 2.0f * p2c * p2s;
        const float p8c = p4c * p4c - p4s * p4s, p8s = 2.0f * p4c * p4s;

        uint64_t Zr[4], Zi[4];
        #pragma unroll
        for (int q = 0; q < 4; ++q) {
            Zr[q] = pk2(zr[2 * q], zr[2 * q + 1]);
            Zi[q] = pk2(zi[2 * q], zi[2 * q + 1]);
        }

        {   // H=16: w = u
            const bool hi = (lane & 16) != 0;
            const float wc = hi ?  uc : 1.0f;
            const float ws = hi ?  us : 0.0f;
            dif_stage_p<16>(Zr, Zi, hi ? NEG2 : ONE2,
                            pk2(wc, wc), pk2(-ws, -ws), pk2(ws, ws));
        }
        {   // H=8: w = -u^2
            const bool hi = (lane & 8) != 0;
            const float wc = hi ? -p2c : 1.0f;
            const float ws = hi ? -p2s : 0.0f;
            dif_stage_p<8>(Zr, Zi, hi ? NEG2 : ONE2,
                           pk2(wc, wc), pk2(-ws, -ws), pk2(ws, ws));
        }
        {   // H=4: w = -u^4
            const bool hi = (lane & 4) != 0;
            const float wc = hi ? -p4c : 1.0f;
            const float ws = hi ? -p4s : 0.0f;
            dif_stage_p<4>(Zr, Zi, hi ? NEG2 : ONE2,
                           pk2(wc, wc), pk2(-ws, -ws), pk2(ws, ws));
        }
        {   // H=2: w = -u^8
            const bool hi = (lane & 2) != 0;
            const float wc = hi ? -p8c : 1.0f;
            const float ws = hi ? -p8s : 0.0f;
            dif_stage_p<2>(Zr, Zi, hi ? NEG2 : ONE2,
                           pk2(wc, wc), pk2(-ws, -ws), pk2(ws, ws));
        }
        {   // H=1: w = 1 (twiddle-free)
            const uint64_t s2 = (lane & 1) ? NEG2 : ONE2;
            #pragma unroll
            for (int q = 0; q < 4; ++q) {
                const uint64_t orr = __shfl_xor_sync(0xffffffffu, Zr[q], 1);
                const uint64_t oii = __shfl_xor_sync(0xffffffffu, Zi[q], 1);
                Zr[q] = fma2(s2, Zr[q], orr);
                Zi[q] = fma2(s2, Zi[q], oii);
            }
        }

        #pragma unroll
        for (int q = 0; q < 4; ++q) {
            upk2(Zr[q], zr[2 * q], zr[2 * q + 1]);
            upk2(Zi[q], zi[2 * q], zi[2 * q + 1]);
        }
    }
    // lane l, slot r now holds 0.5 * Z[k2 + 8*kappa], k2 = br3(r), kappa = br5(l)

    const int kap = __brev((unsigned)lane) >> 27;   // bitrev5(lane)

    // ---- untangle X[k] = Fe + W_512^k Fo for k = 8*kappa + d, via shuffles ----
    {
        float bc, bs;   // W_64^kappa = exp(-i pi kappa / 32)
        __sincosf(-CUDART_PI_F * (float)kap / 32.0f, &bs, &bc);

        // Cd = exp(-i pi d / 256) = (cd, -sd)
        const float CDC[8] = {1.0f, 0.99992470183914454f, 0.99969881869620420f,
                              0.99932238458834950f, 0.99879545620517240f,
                              0.99811811290014920f, 0.99729045667869020f,
                              0.99631261218277800f};
        const float CDS[8] = {0.0f, 0.012271538285719925f, 0.024541228522912288f,
                              0.036807222941358832f, 0.049067674327418015f,
                              0.061320736302208578f, 0.073564563599667426f,
                              0.085797312344439894f};
        const int IZ[8] = {0, 4, 2, 6, 1, 5, 3, 7};   // slot holding k2 = d
        const int SM[8] = {0, 7, 3, 5, 1, 6, 2, 4};   // slot holding k2 = 8-d

        // d=0 partner: kappa' = (32-kappa)&31 lives on lane br5(kappa')
        const int src0 = __brev((unsigned)((32 - kap) & 31)) >> 27;

        #pragma unroll
        for (int d = 0; d < 8; ++d) {
            const float zkr = zr[IZ[d]], zki = zi[IZ[d]];
            float zmr, zmi;
            if (d == 0) {
                zmr = __shfl_sync(0xffffffffu, zr[0], src0);
                zmi = __shfl_sync(0xffffffffu, zi[0], src0);
            } else {
                zmr = __shfl_xor_sync(0xffffffffu, zr[SM[d]], 31);
                zmi = __shfl_xor_sync(0xffffffffu, zi[SM[d]], 31);
            }
            // W_512^{8kappa+d} = (bc + i bs)(cd - i sd)
            const float wc = (d == 0) ? bc : fmaf(bc, CDC[d],  bs * CDS[d]);
            const float ws = (d == 0) ? bs : fmaf(bs, CDC[d], -bc * CDS[d]);

            const float Fer = zkr + zmr;
            const float Fei = zki - zmi;
            const float For = zki + zmi;
            const float Foi = zmr - zkr;

            sxr[w][36 * d + kap] = fmaf(wc, For, fmaf(-ws, Foi, Fer));
            sxi[w][36 * d + kap] = fmaf(wc, Foi, fmaf( ws, For, Fei));
        }
    }

    float* orow = yre + row * NOUT;
    float* irow = yim + row * NOUT;

    if (lane == 0) {   // bin 256: X[256] = Re(Z0) - Im(Z0); z holds 0.5*Z
        orow[256] = 2.0f * (zr[0] - zi[0]);
        irow[256] = 0.0f;
    }
    __syncwarp();

    // ---- coalesced stores: X[32j + lane] from idx 36*(lane&7) + 4j + (lane>>3) ----
    #pragma unroll
    for (int j = 0; j < 8; ++j) {
        const int idx = 36 * (lane & 7) + 4 * j + (lane >> 3);
        const int k   = 32 * j + lane;
        orow[k] = sxr[w][idx];
        irow[k] = sxi[w][idx];
    }
}

extern "C" void kernel_launch(void* const* d_in, const int* in_sizes, int n_in,
                              void* d_out, int out_size)
{
    const float* x = (const float*)d_in[0];
    float* out = (float*)d_out;
    float* yre = out;                                  // [32768, 257]
    float* yim = out + (long long)NBATCH * NOUT;       // [32768, 257]

    rfft512_warp<<<NBATCH / RPB, 32 * RPB>>>(x, yre, yim);
}